// round 1
// baseline (speedup 1.0000x reference)
#include <cuda_runtime.h>
#include <cuda_bf16.h>
#include <cstdint>

// ---------------------------------------------------------------------------
// GraphAttentionLayer: N=4096, F=512, H=8, d=64
//   QKV = x @ W^T (bf16 mma, fp32 accum), Q pre-scaled by 1/sqrt(512)
//   flash-attention per (head, 128-row q block), adj mask read from gmem
//   out = elu(attn + x)
// ---------------------------------------------------------------------------

#define NN 4096
#define FF 512
#define NH 8
#define HD 64

__device__ __nv_bfloat16 g_Q[NN * FF];
__device__ __nv_bfloat16 g_K[NN * FF];
__device__ __nv_bfloat16 g_V[NN * FF];

__device__ __forceinline__ uint32_t smem_u32(const void* p) {
    return (uint32_t)__cvta_generic_to_shared(p);
}

__device__ __forceinline__ void ldsm_x4(uint32_t addr, uint32_t& r0, uint32_t& r1,
                                        uint32_t& r2, uint32_t& r3) {
    asm volatile("ldmatrix.sync.aligned.m8n8.x4.shared.b16 {%0,%1,%2,%3}, [%4];"
                 : "=r"(r0), "=r"(r1), "=r"(r2), "=r"(r3) : "r"(addr));
}

__device__ __forceinline__ void ldsm_x4_t(uint32_t addr, uint32_t& r0, uint32_t& r1,
                                          uint32_t& r2, uint32_t& r3) {
    asm volatile("ldmatrix.sync.aligned.m8n8.x4.trans.shared.b16 {%0,%1,%2,%3}, [%4];"
                 : "=r"(r0), "=r"(r1), "=r"(r2), "=r"(r3) : "r"(addr));
}

__device__ __forceinline__ void mma16816(float* d, const uint32_t* a, uint32_t b0, uint32_t b1) {
    asm volatile("mma.sync.aligned.m16n8k16.row.col.f32.bf16.bf16.f32 "
                 "{%0,%1,%2,%3}, {%4,%5,%6,%7}, {%8,%9}, {%0,%1,%2,%3};"
                 : "+f"(d[0]), "+f"(d[1]), "+f"(d[2]), "+f"(d[3])
                 : "r"(a[0]), "r"(a[1]), "r"(a[2]), "r"(a[3]), "r"(b0), "r"(b1));
}

// pack two f32 -> bf16x2 (lo in low half)
__device__ __forceinline__ uint32_t packbf(float lo, float hi) {
    uint32_t r;
    asm("cvt.rn.bf16x2.f32 %0, %1, %2;" : "=r"(r) : "f"(hi), "f"(lo));
    return r;
}

// ---------------------------------------------------------------------------
// Projection GEMM: C[i,j] = sum_k A[i,k] * W[j,k]   (A=x [4096,512], W [512,512])
// Tile 128x128x32, 256 threads (8 warps, 4x2), bf16 mma, bf16 output.
// grid = (32, 12): blockIdx.y>>2 selects matrix (Q/K/V), &3 selects n-block.
// ---------------------------------------------------------------------------
__global__ __launch_bounds__(256) void proj_kernel(const float* __restrict__ x,
                                                   const float* __restrict__ Wq,
                                                   const float* __restrict__ Wk,
                                                   const float* __restrict__ Wv) {
    __shared__ __nv_bfloat16 sA[128][40];
    __shared__ __nv_bfloat16 sB[128][40];

    const int tid = threadIdx.x;
    const int lane = tid & 31;
    const int warp = tid >> 5;
    const int wr = warp & 3;       // m warp (4)
    const int wc = warp >> 2;      // n warp (2)
    const int mblk = blockIdx.x;
    const int mat = blockIdx.y >> 2;
    const int nblk = blockIdx.y & 3;

    const float* W = (mat == 0) ? Wq : (mat == 1) ? Wk : Wv;
    __nv_bfloat16* dst = (mat == 0) ? g_Q : (mat == 1) ? g_K : g_V;
    const float scale = (mat == 0) ? 0.044194173824159216f : 1.0f;  // 1/sqrt(512) folded into Q

    float acc[2][8][4];
#pragma unroll
    for (int mt = 0; mt < 2; ++mt)
#pragma unroll
        for (int t = 0; t < 8; ++t)
#pragma unroll
            for (int i = 0; i < 4; ++i) acc[mt][t][i] = 0.f;

    const int lr = tid >> 3;          // 0..31
    const int lc = (tid & 7) * 4;     // 0..28

    for (int kt = 0; kt < 16; ++kt) {
        const int k0 = kt * 32;
        __syncthreads();
#pragma unroll
        for (int p = 0; p < 4; ++p) {
            const int r = lr + p * 32;
            float4 av = *(const float4*)(x + (size_t)(mblk * 128 + r) * FF + k0 + lc);
            *(__nv_bfloat162*)&sA[r][lc]     = __floats2bfloat162_rn(av.x, av.y);
            *(__nv_bfloat162*)&sA[r][lc + 2] = __floats2bfloat162_rn(av.z, av.w);
            float4 bv = *(const float4*)(W + (size_t)(nblk * 128 + r) * FF + k0 + lc);
            *(__nv_bfloat162*)&sB[r][lc]     = __floats2bfloat162_rn(bv.x, bv.y);
            *(__nv_bfloat162*)&sB[r][lc + 2] = __floats2bfloat162_rn(bv.z, bv.w);
        }
        __syncthreads();

#pragma unroll
        for (int ks = 0; ks < 2; ++ks) {
            uint32_t af[2][4];
#pragma unroll
            for (int mt = 0; mt < 2; ++mt) {
                const int row = wr * 32 + mt * 16 + (lane & 7) + ((lane >> 3) & 1) * 8;
                const int col = ks * 16 + (lane >> 4) * 8;
                ldsm_x4(smem_u32(&sA[row][col]), af[mt][0], af[mt][1], af[mt][2], af[mt][3]);
            }
#pragma unroll
            for (int g = 0; g < 4; ++g) {
                const int row = wc * 64 + g * 16 + (lane & 7) + (lane >> 4) * 8;
                const int col = ks * 16 + ((lane >> 3) & 1) * 8;
                uint32_t b0, b1, b2, b3;
                ldsm_x4(smem_u32(&sB[row][col]), b0, b1, b2, b3);
#pragma unroll
                for (int mt = 0; mt < 2; ++mt) {
                    mma16816(acc[mt][2 * g],     af[mt], b0, b1);
                    mma16816(acc[mt][2 * g + 1], af[mt], b2, b3);
                }
            }
        }
    }

#pragma unroll
    for (int mt = 0; mt < 2; ++mt) {
        const int row = mblk * 128 + wr * 32 + mt * 16 + (lane >> 2);
#pragma unroll
        for (int t = 0; t < 8; ++t) {
            const int col = nblk * 128 + wc * 64 + t * 8 + (lane & 3) * 2;
            *(uint32_t*)&dst[(size_t)row * FF + col] =
                packbf(acc[mt][t][0] * scale, acc[mt][t][1] * scale);
            *(uint32_t*)&dst[(size_t)(row + 8) * FF + col] =
                packbf(acc[mt][t][2] * scale, acc[mt][t][3] * scale);
        }
    }
}

// ---------------------------------------------------------------------------
// Flash attention. grid = (32 q-blocks, 8 heads), 256 threads (8 warps).
// Each warp owns 16 q rows; KV tiled 64 at a time. adj masked in-register.
// ---------------------------------------------------------------------------
__global__ __launch_bounds__(256) void attn_kernel(const float* __restrict__ x,
                                                   const int* __restrict__ adj,
                                                   float* __restrict__ out) {
    __shared__ __nv_bfloat16 sQ[128][72];
    __shared__ __nv_bfloat16 sK[64][72];
    __shared__ __nv_bfloat16 sV[64][72];

    const int tid = threadIdx.x;
    const int lane = tid & 31;
    const int warp = tid >> 5;
    const int q0 = blockIdx.x * 128;
    const int h = blockIdx.y;
    const int hc = h * HD;

    // load Q tile (128 x 64 bf16)
    {
        const int r = tid >> 3;
        const int c8 = (tid & 7) * 8;
#pragma unroll
        for (int p = 0; p < 4; ++p) {
            uint4 v = *(const uint4*)(g_Q + (size_t)(q0 + r + p * 32) * FF + hc + c8);
            *(uint4*)&sQ[r + p * 32][c8] = v;
        }
    }
    __syncthreads();

    const int rw = warp * 16;
    uint32_t qf[4][4];
#pragma unroll
    for (int ks = 0; ks < 4; ++ks) {
        const int row = rw + (lane & 7) + ((lane >> 3) & 1) * 8;
        const int col = ks * 16 + (lane >> 4) * 8;
        ldsm_x4(smem_u32(&sQ[row][col]), qf[ks][0], qf[ks][1], qf[ks][2], qf[ks][3]);
    }

    float O[8][4];
#pragma unroll
    for (int t = 0; t < 8; ++t)
#pragma unroll
        for (int i = 0; i < 4; ++i) O[t][i] = 0.f;

    float m0 = -9e15f, m1 = -9e15f, l0 = 0.f, l1 = 0.f;

    const int lr = tid >> 3;
    const int lc8 = (tid & 7) * 8;
    const long adjbase = ((long)h * NN + (q0 + rw + (lane >> 2))) * (long)NN;

    for (int jt = 0; jt < 64; ++jt) {
        const int j0 = jt * 64;
        __syncthreads();
#pragma unroll
        for (int p = 0; p < 2; ++p) {
            uint4 kv = *(const uint4*)(g_K + (size_t)(j0 + lr + p * 32) * FF + hc + lc8);
            *(uint4*)&sK[lr + p * 32][lc8] = kv;
            uint4 vv = *(const uint4*)(g_V + (size_t)(j0 + lr + p * 32) * FF + hc + lc8);
            *(uint4*)&sV[lr + p * 32][lc8] = vv;
        }
        __syncthreads();

        // S = Q K^T (already scaled via Q)
        float s[8][4];
#pragma unroll
        for (int t = 0; t < 8; ++t)
#pragma unroll
            for (int i = 0; i < 4; ++i) s[t][i] = 0.f;

#pragma unroll
        for (int ks = 0; ks < 4; ++ks) {
#pragma unroll
            for (int g = 0; g < 4; ++g) {
                const int row = g * 16 + (lane & 7) + (lane >> 4) * 8;
                const int col = ks * 16 + ((lane >> 3) & 1) * 8;
                uint32_t b0, b1, b2, b3;
                ldsm_x4(smem_u32(&sK[row][col]), b0, b1, b2, b3);
                mma16816(s[2 * g],     qf[ks], b0, b1);
                mma16816(s[2 * g + 1], qf[ks], b2, b3);
            }
        }

        // mask with adj (rows r and r+8 of this warp's 16-row band)
        const int2* a0p = (const int2*)(adj + adjbase + j0);
        const int2* a1p = (const int2*)(adj + adjbase + 8L * NN + j0);
        const int ci = lane & 3;
#pragma unroll
        for (int t = 0; t < 8; ++t) {
            int2 a0 = __ldg(a0p + t * 4 + ci);
            int2 a1 = __ldg(a1p + t * 4 + ci);
            s[t][0] = (a0.x > 0) ? s[t][0] : -9e15f;
            s[t][1] = (a0.y > 0) ? s[t][1] : -9e15f;
            s[t][2] = (a1.x > 0) ? s[t][2] : -9e15f;
            s[t][3] = (a1.y > 0) ? s[t][3] : -9e15f;
        }

        // online softmax (rows owned by lane quads)
        float mx0 = s[0][0], mx1 = s[0][2];
#pragma unroll
        for (int t = 0; t < 8; ++t) {
            mx0 = fmaxf(mx0, fmaxf(s[t][0], s[t][1]));
            mx1 = fmaxf(mx1, fmaxf(s[t][2], s[t][3]));
        }
        mx0 = fmaxf(mx0, __shfl_xor_sync(0xffffffffu, mx0, 1));
        mx0 = fmaxf(mx0, __shfl_xor_sync(0xffffffffu, mx0, 2));
        mx1 = fmaxf(mx1, __shfl_xor_sync(0xffffffffu, mx1, 1));
        mx1 = fmaxf(mx1, __shfl_xor_sync(0xffffffffu, mx1, 2));

        const float mn0 = fmaxf(m0, mx0);
        const float mn1 = fmaxf(m1, mx1);
        const float f0 = __expf(m0 - mn0);
        const float f1 = __expf(m1 - mn1);
        m0 = mn0; m1 = mn1;

        float sum0 = 0.f, sum1 = 0.f;
#pragma unroll
        for (int t = 0; t < 8; ++t) {
            s[t][0] = __expf(s[t][0] - mn0); sum0 += s[t][0];
            s[t][1] = __expf(s[t][1] - mn0); sum0 += s[t][1];
            s[t][2] = __expf(s[t][2] - mn1); sum1 += s[t][2];
            s[t][3] = __expf(s[t][3] - mn1); sum1 += s[t][3];
        }
        sum0 += __shfl_xor_sync(0xffffffffu, sum0, 1);
        sum0 += __shfl_xor_sync(0xffffffffu, sum0, 2);
        sum1 += __shfl_xor_sync(0xffffffffu, sum1, 1);
        sum1 += __shfl_xor_sync(0xffffffffu, sum1, 2);
        l0 = l0 * f0 + sum0;
        l1 = l1 * f1 + sum1;

#pragma unroll
        for (int t = 0; t < 8; ++t) {
            O[t][0] *= f0; O[t][1] *= f0;
            O[t][2] *= f1; O[t][3] *= f1;
        }

        // O += P @ V
#pragma unroll
        for (int kg = 0; kg < 4; ++kg) {
            uint32_t pa[4];
            pa[0] = packbf(s[2 * kg][0],     s[2 * kg][1]);
            pa[1] = packbf(s[2 * kg][2],     s[2 * kg][3]);
            pa[2] = packbf(s[2 * kg + 1][0], s[2 * kg + 1][1]);
            pa[3] = packbf(s[2 * kg + 1][2], s[2 * kg + 1][3]);
#pragma unroll
            for (int dg = 0; dg < 4; ++dg) {
                const int row = kg * 16 + (lane & 7) + ((lane >> 3) & 1) * 8;
                const int col = dg * 16 + (lane >> 4) * 8;
                uint32_t b0, b1, b2, b3;
                ldsm_x4_t(smem_u32(&sV[row][col]), b0, b1, b2, b3);
                mma16816(O[2 * dg],     pa, b0, b1);
                mma16816(O[2 * dg + 1], pa, b2, b3);
            }
        }
    }

    // epilogue: normalize, residual, ELU
    const float inv0 = 1.f / l0;
    const float inv1 = 1.f / l1;
    const int r0 = q0 + rw + (lane >> 2);
    const int r1 = r0 + 8;
#pragma unroll
    for (int t = 0; t < 8; ++t) {
        const int col = hc + t * 8 + (lane & 3) * 2;
        float2 x0 = *(const float2*)(x + (size_t)r0 * FF + col);
        float2 x1 = *(const float2*)(x + (size_t)r1 * FF + col);
        float v00 = O[t][0] * inv0 + x0.x;
        float v01 = O[t][1] * inv0 + x0.y;
        float v10 = O[t][2] * inv1 + x1.x;
        float v11 = O[t][3] * inv1 + x1.y;
        v00 = (v00 > 0.f) ? v00 : expm1f(v00);
        v01 = (v01 > 0.f) ? v01 : expm1f(v01);
        v10 = (v10 > 0.f) ? v10 : expm1f(v10);
        v11 = (v11 > 0.f) ? v11 : expm1f(v11);
        *(float2*)(out + (size_t)r0 * FF + col) = make_float2(v00, v01);
        *(float2*)(out + (size_t)r1 * FF + col) = make_float2(v10, v11);
    }
}

extern "C" void kernel_launch(void* const* d_in, const int* in_sizes, int n_in,
                              void* d_out, int out_size) {
    const float* x  = (const float*)d_in[0];
    const float* Wq = (const float*)d_in[1];
    const float* Wk = (const float*)d_in[2];
    const float* Wv = (const float*)d_in[3];
    const int* adj  = (const int*)d_in[4];
    float* out = (float*)d_out;

    proj_kernel<<<dim3(32, 12), 256>>>(x, Wq, Wk, Wv);
    attn_kernel<<<dim3(32, 8), 256>>>(x, adj, out);
}

// round 2
// speedup vs baseline: 1.5121x; 1.5121x over previous
#include <cuda_runtime.h>
#include <cuda_bf16.h>
#include <cstdint>

// ---------------------------------------------------------------------------
// GraphAttentionLayer: N=4096, F=512, H=8, d=64
//  1) pack_kernel: adj int32 [8,4096,4096] -> bitmask (16 MB, L2-resident)
//  2) proj_kernel: Q/K/V = x @ W^T (bf16 mma), Q scaled by log2e/sqrt(512)
//  3) attn_kernel: flash attention, bitmask masking, cp.async double buffer
// ---------------------------------------------------------------------------

#define NN 4096
#define FF 512
#define NH 8
#define HD 64

__device__ __nv_bfloat16 g_Q[NN * FF];
__device__ __nv_bfloat16 g_K[NN * FF];
__device__ __nv_bfloat16 g_V[NN * FF];
__device__ uint32_t g_mask[NH * NN * (NN / 32)];   // 16 MB

__device__ __forceinline__ uint32_t smem_u32(const void* p) {
    return (uint32_t)__cvta_generic_to_shared(p);
}

__device__ __forceinline__ void ldsm_x4(uint32_t addr, uint32_t& r0, uint32_t& r1,
                                        uint32_t& r2, uint32_t& r3) {
    asm volatile("ldmatrix.sync.aligned.m8n8.x4.shared.b16 {%0,%1,%2,%3}, [%4];"
                 : "=r"(r0), "=r"(r1), "=r"(r2), "=r"(r3) : "r"(addr));
}

__device__ __forceinline__ void ldsm_x4_t(uint32_t addr, uint32_t& r0, uint32_t& r1,
                                          uint32_t& r2, uint32_t& r3) {
    asm volatile("ldmatrix.sync.aligned.m8n8.x4.trans.shared.b16 {%0,%1,%2,%3}, [%4];"
                 : "=r"(r0), "=r"(r1), "=r"(r2), "=r"(r3) : "r"(addr));
}

__device__ __forceinline__ void mma16816(float* d, const uint32_t* a, uint32_t b0, uint32_t b1) {
    asm volatile("mma.sync.aligned.m16n8k16.row.col.f32.bf16.bf16.f32 "
                 "{%0,%1,%2,%3}, {%4,%5,%6,%7}, {%8,%9}, {%0,%1,%2,%3};"
                 : "+f"(d[0]), "+f"(d[1]), "+f"(d[2]), "+f"(d[3])
                 : "r"(a[0]), "r"(a[1]), "r"(a[2]), "r"(a[3]), "r"(b0), "r"(b1));
}

__device__ __forceinline__ uint32_t packbf(float lo, float hi) {
    uint32_t r;
    asm("cvt.rn.bf16x2.f32 %0, %1, %2;" : "=r"(r) : "f"(hi), "f"(lo));
    return r;
}

__device__ __forceinline__ float ex2(float x) {
    float r;
    asm("ex2.approx.ftz.f32 %0, %1;" : "=f"(r) : "f"(x));
    return r;
}

__device__ __forceinline__ void cp16(void* s, const void* g) {
    asm volatile("cp.async.cg.shared.global [%0], [%1], 16;"
                 :: "r"(smem_u32(s)), "l"(g));
}
__device__ __forceinline__ void cp_commit() { asm volatile("cp.async.commit_group;"); }
template <int n>
__device__ __forceinline__ void cp_wait() { asm volatile("cp.async.wait_group %0;" :: "n"(n)); }

// ---------------------------------------------------------------------------
// Pack adj -> bitmask. Warp-tile = 128 cols (512 B contiguous read -> 4 words).
// ---------------------------------------------------------------------------
__global__ __launch_bounds__(256) void pack_kernel(const int* __restrict__ adj) {
    const int lane = threadIdx.x & 31;
    const int wg = (blockIdx.x * blockDim.x + threadIdx.x) >> 5;   // global warp
    const int nw = (gridDim.x * blockDim.x) >> 5;
    const int grp = lane >> 3;
    const int shift = (lane & 7) * 4;
    const int total = NH * NN * (NN / 128);                        // 1048576 tiles

    for (int T = wg * 2; T < total; T += nw * 2) {
#pragma unroll
        for (int u = 0; u < 2; ++u) {
            const int t = T + u;
            int4 v = __ldg((const int4*)(adj + (size_t)t * 128) + lane);
            uint32_t w = ((uint32_t)(v.x > 0) | ((uint32_t)(v.y > 0) << 1) |
                          ((uint32_t)(v.z > 0) << 2) | ((uint32_t)(v.w > 0) << 3)) << shift;
            w |= __shfl_xor_sync(0xffffffffu, w, 1);
            w |= __shfl_xor_sync(0xffffffffu, w, 2);
            w |= __shfl_xor_sync(0xffffffffu, w, 4);
            if ((lane & 7) == 0) g_mask[(size_t)t * 4 + grp] = w;
        }
    }
}

// ---------------------------------------------------------------------------
// Projection GEMM (unchanged from R1 except Q scale now includes log2e)
// ---------------------------------------------------------------------------
__global__ __launch_bounds__(256) void proj_kernel(const float* __restrict__ x,
                                                   const float* __restrict__ Wq,
                                                   const float* __restrict__ Wk,
                                                   const float* __restrict__ Wv) {
    __shared__ __nv_bfloat16 sA[128][40];
    __shared__ __nv_bfloat16 sB[128][40];

    const int tid = threadIdx.x;
    const int lane = tid & 31;
    const int warp = tid >> 5;
    const int wr = warp & 3;
    const int wc = warp >> 2;
    const int mblk = blockIdx.x;
    const int mat = blockIdx.y >> 2;
    const int nblk = blockIdx.y & 3;

    const float* W = (mat == 0) ? Wq : (mat == 1) ? Wk : Wv;
    __nv_bfloat16* dst = (mat == 0) ? g_Q : (mat == 1) ? g_K : g_V;
    // Q scale = 1/sqrt(512) * log2(e)  (softmax done in base-2)
    const float scale = (mat == 0) ? (0.044194173824159216f * 1.4426950408889634f) : 1.0f;

    float acc[2][8][4];
#pragma unroll
    for (int mt = 0; mt < 2; ++mt)
#pragma unroll
        for (int t = 0; t < 8; ++t)
#pragma unroll
            for (int i = 0; i < 4; ++i) acc[mt][t][i] = 0.f;

    const int lr = tid >> 3;
    const int lc = (tid & 7) * 4;

    for (int kt = 0; kt < 16; ++kt) {
        const int k0 = kt * 32;
        __syncthreads();
#pragma unroll
        for (int p = 0; p < 4; ++p) {
            const int r = lr + p * 32;
            float4 av = *(const float4*)(x + (size_t)(mblk * 128 + r) * FF + k0 + lc);
            *(__nv_bfloat162*)&sA[r][lc]     = __floats2bfloat162_rn(av.x, av.y);
            *(__nv_bfloat162*)&sA[r][lc + 2] = __floats2bfloat162_rn(av.z, av.w);
            float4 bv = *(const float4*)(W + (size_t)(nblk * 128 + r) * FF + k0 + lc);
            *(__nv_bfloat162*)&sB[r][lc]     = __floats2bfloat162_rn(bv.x, bv.y);
            *(__nv_bfloat162*)&sB[r][lc + 2] = __floats2bfloat162_rn(bv.z, bv.w);
        }
        __syncthreads();

#pragma unroll
        for (int ks = 0; ks < 2; ++ks) {
            uint32_t af[2][4];
#pragma unroll
            for (int mt = 0; mt < 2; ++mt) {
                const int row = wr * 32 + mt * 16 + (lane & 7) + ((lane >> 3) & 1) * 8;
                const int col = ks * 16 + (lane >> 4) * 8;
                ldsm_x4(smem_u32(&sA[row][col]), af[mt][0], af[mt][1], af[mt][2], af[mt][3]);
            }
#pragma unroll
            for (int g = 0; g < 4; ++g) {
                const int row = wc * 64 + g * 16 + (lane & 7) + (lane >> 4) * 8;
                const int col = ks * 16 + ((lane >> 3) & 1) * 8;
                uint32_t b0, b1, b2, b3;
                ldsm_x4(smem_u32(&sB[row][col]), b0, b1, b2, b3);
#pragma unroll
                for (int mt = 0; mt < 2; ++mt) {
                    mma16816(acc[mt][2 * g],     af[mt], b0, b1);
                    mma16816(acc[mt][2 * g + 1], af[mt], b2, b3);
                }
            }
        }
    }

#pragma unroll
    for (int mt = 0; mt < 2; ++mt) {
        const int row = mblk * 128 + wr * 32 + mt * 16 + (lane >> 2);
#pragma unroll
        for (int t = 0; t < 8; ++t) {
            const int col = nblk * 128 + wc * 64 + t * 8 + (lane & 3) * 2;
            *(uint32_t*)&dst[(size_t)row * FF + col] =
                packbf(acc[mt][t][0] * scale, acc[mt][t][1] * scale);
            *(uint32_t*)&dst[(size_t)(row + 8) * FF + col] =
                packbf(acc[mt][t][2] * scale, acc[mt][t][3] * scale);
        }
    }
}

// ---------------------------------------------------------------------------
// Flash attention, bitmask masking, cp.async double-buffered K/V.
// grid=(32,8), 256 threads (8 warps x 16 q rows). Softmax in base-2.
// ---------------------------------------------------------------------------
__global__ __launch_bounds__(256, 2) void attn_kernel(const float* __restrict__ x,
                                                      float* __restrict__ out) {
    __shared__ __nv_bfloat16 sK[2][64][72];
    __shared__ __nv_bfloat16 sV[2][64][72];

    const int tid = threadIdx.x;
    const int lane = tid & 31;
    const int warp = tid >> 5;
    const int q0 = blockIdx.x * 128;
    const int h = blockIdx.y;
    const int hc = h * HD;

    const int lr = tid >> 3;           // 0..31
    const int lc8 = (tid & 7) * 8;     // 0..56

    // --- stage Q (128x64) into sK[0]/sV[0], pull fragments, then free ---
    {
#pragma unroll
        for (int p = 0; p < 4; ++p) {
            const int r = lr + p * 32;
            uint4 v = *(const uint4*)(g_Q + (size_t)(q0 + r) * FF + hc + lc8);
            if (r < 64) *(uint4*)&sK[0][r][lc8] = v;
            else        *(uint4*)&sV[0][r - 64][lc8] = v;
        }
    }
    __syncthreads();

    const int rw = warp * 16;
    uint32_t qf[4][4];
#pragma unroll
    for (int ks = 0; ks < 4; ++ks) {
        const int row = rw + (lane & 7) + ((lane >> 3) & 1) * 8;
        const int col = ks * 16 + (lane >> 4) * 8;
        const __nv_bfloat16* src = (row < 64) ? &sK[0][row][col] : &sV[0][row - 64][col];
        ldsm_x4(smem_u32(src), qf[ks][0], qf[ks][1], qf[ks][2], qf[ks][3]);
    }
    __syncthreads();

    float O[8][4];
#pragma unroll
    for (int t = 0; t < 8; ++t)
#pragma unroll
        for (int i = 0; i < 4; ++i) O[t][i] = 0.f;

    float m0 = -9e15f, m1 = -9e15f, l0 = 0.f, l1 = 0.f;

    const int cq = lane & 3;
    const int r0g = q0 + rw + (lane >> 2);             // global q row (first of pair)
    const size_t mrow0 = ((size_t)h * NN + r0g) * (NN / 32);
    const size_t mrow1 = mrow0 + 8 * (NN / 32);

    // prologue: async-load tile 0
#pragma unroll
    for (int p = 0; p < 2; ++p) {
        const int r = lr + p * 32;
        cp16(&sK[0][r][lc8], g_K + (size_t)r * FF + hc + lc8);
        cp16(&sV[0][r][lc8], g_V + (size_t)r * FF + hc + lc8);
    }
    cp_commit();

    for (int jt = 0; jt < 64; ++jt) {
        const int cur = jt & 1;

        // prefetch mask words for this tile (2 x uint64)
        uint64_t u0 = (*(const uint64_t*)(g_mask + mrow0 + 2 * jt)) >> (2 * cq);
        uint64_t u1 = (*(const uint64_t*)(g_mask + mrow1 + 2 * jt)) >> (2 * cq);

        // prefetch next K/V tile
        if (jt < 63) {
            const int j1 = (jt + 1) * 64;
#pragma unroll
            for (int p = 0; p < 2; ++p) {
                const int r = lr + p * 32;
                cp16(&sK[cur ^ 1][r][lc8], g_K + (size_t)(j1 + r) * FF + hc + lc8);
                cp16(&sV[cur ^ 1][r][lc8], g_V + (size_t)(j1 + r) * FF + hc + lc8);
            }
            cp_commit();
            cp_wait<1>();
        } else {
            cp_wait<0>();
        }
        __syncthreads();

        // S = Q K^T (base-2 scaled already)
        float s[8][4];
#pragma unroll
        for (int t = 0; t < 8; ++t)
#pragma unroll
            for (int i = 0; i < 4; ++i) s[t][i] = 0.f;

#pragma unroll
        for (int ks = 0; ks < 4; ++ks) {
#pragma unroll
            for (int g = 0; g < 4; ++g) {
                const int row = g * 16 + (lane & 7) + (lane >> 4) * 8;
                const int col = ks * 16 + ((lane >> 3) & 1) * 8;
                uint32_t b0, b1, b2, b3;
                ldsm_x4(smem_u32(&sK[cur][row][col]), b0, b1, b2, b3);
                mma16816(s[2 * g],     qf[ks], b0, b1);
                mma16816(s[2 * g + 1], qf[ks], b2, b3);
            }
        }

        // mask via bits
#pragma unroll
        for (int t = 0; t < 8; ++t) {
            s[t][0] = ((u0 >> (8 * t)) & 1)     ? s[t][0] : -9e15f;
            s[t][1] = ((u0 >> (8 * t + 1)) & 1) ? s[t][1] : -9e15f;
            s[t][2] = ((u1 >> (8 * t)) & 1)     ? s[t][2] : -9e15f;
            s[t][3] = ((u1 >> (8 * t + 1)) & 1) ? s[t][3] : -9e15f;
        }

        // online softmax (base-2)
        float mx0 = s[0][0], mx1 = s[0][2];
#pragma unroll
        for (int t = 0; t < 8; ++t) {
            mx0 = fmaxf(mx0, fmaxf(s[t][0], s[t][1]));
            mx1 = fmaxf(mx1, fmaxf(s[t][2], s[t][3]));
        }
        mx0 = fmaxf(mx0, __shfl_xor_sync(0xffffffffu, mx0, 1));
        mx0 = fmaxf(mx0, __shfl_xor_sync(0xffffffffu, mx0, 2));
        mx1 = fmaxf(mx1, __shfl_xor_sync(0xffffffffu, mx1, 1));
        mx1 = fmaxf(mx1, __shfl_xor_sync(0xffffffffu, mx1, 2));

        const float mn0 = fmaxf(m0, mx0);
        const float mn1 = fmaxf(m1, mx1);
        const float f0 = ex2(m0 - mn0);
        const float f1 = ex2(m1 - mn1);
        m0 = mn0; m1 = mn1;

        float sum0 = 0.f, sum1 = 0.f;
#pragma unroll
        for (int t = 0; t < 8; ++t) {
            s[t][0] = ex2(s[t][0] - mn0); sum0 += s[t][0];
            s[t][1] = ex2(s[t][1] - mn0); sum0 += s[t][1];
            s[t][2] = ex2(s[t][2] - mn1); sum1 += s[t][2];
            s[t][3] = ex2(s[t][3] - mn1); sum1 += s[t][3];
        }
        sum0 += __shfl_xor_sync(0xffffffffu, sum0, 1);
        sum0 += __shfl_xor_sync(0xffffffffu, sum0, 2);
        sum1 += __shfl_xor_sync(0xffffffffu, sum1, 1);
        sum1 += __shfl_xor_sync(0xffffffffu, sum1, 2);
        l0 = l0 * f0 + sum0;
        l1 = l1 * f1 + sum1;

#pragma unroll
        for (int t = 0; t < 8; ++t) {
            O[t][0] *= f0; O[t][1] *= f0;
            O[t][2] *= f1; O[t][3] *= f1;
        }

        // O += P @ V
#pragma unroll
        for (int kg = 0; kg < 4; ++kg) {
            uint32_t pa[4];
            pa[0] = packbf(s[2 * kg][0],     s[2 * kg][1]);
            pa[1] = packbf(s[2 * kg][2],     s[2 * kg][3]);
            pa[2] = packbf(s[2 * kg + 1][0], s[2 * kg + 1][1]);
            pa[3] = packbf(s[2 * kg + 1][2], s[2 * kg + 1][3]);
#pragma unroll
            for (int dg = 0; dg < 4; ++dg) {
                const int row = kg * 16 + (lane & 7) + ((lane >> 3) & 1) * 8;
                const int col = dg * 16 + (lane >> 4) * 8;
                uint32_t b0, b1, b2, b3;
                ldsm_x4_t(smem_u32(&sV[cur][row][col]), b0, b1, b2, b3);
                mma16816(O[2 * dg],     pa, b0, b1);
                mma16816(O[2 * dg + 1], pa, b2, b3);
            }
        }
        __syncthreads();
    }

    // epilogue: normalize, residual, ELU
    const float inv0 = 1.f / l0;
    const float inv1 = 1.f / l1;
    const int r0 = r0g;
    const int r1 = r0 + 8;
#pragma unroll
    for (int t = 0; t < 8; ++t) {
        const int col = hc + t * 8 + (lane & 3) * 2;
        float2 x0 = *(const float2*)(x + (size_t)r0 * FF + col);
        float2 x1 = *(const float2*)(x + (size_t)r1 * FF + col);
        float v00 = O[t][0] * inv0 + x0.x;
        float v01 = O[t][1] * inv0 + x0.y;
        float v10 = O[t][2] * inv1 + x1.x;
        float v11 = O[t][3] * inv1 + x1.y;
        v00 = (v00 > 0.f) ? v00 : expm1f(v00);
        v01 = (v01 > 0.f) ? v01 : expm1f(v01);
        v10 = (v10 > 0.f) ? v10 : expm1f(v10);
        v11 = (v11 > 0.f) ? v11 : expm1f(v11);
        *(float2*)(out + (size_t)r0 * FF + col) = make_float2(v00, v01);
        *(float2*)(out + (size_t)r1 * FF + col) = make_float2(v10, v11);
    }
}

extern "C" void kernel_launch(void* const* d_in, const int* in_sizes, int n_in,
                              void* d_out, int out_size) {
    const float* x  = (const float*)d_in[0];
    const float* Wq = (const float*)d_in[1];
    const float* Wk = (const float*)d_in[2];
    const float* Wv = (const float*)d_in[3];
    const int* adj  = (const int*)d_in[4];
    float* out = (float*)d_out;

    pack_kernel<<<2048, 256>>>(adj);
    proj_kernel<<<dim3(32, 12), 256>>>(x, Wq, Wk, Wv);
    attn_kernel<<<dim3(32, 8), 256>>>(x, out);
}